// round 13
// baseline (speedup 1.0000x reference)
#include <cuda_runtime.h>

// Problem constants
#define B       8
#define C       64
#define G       8
#define FPG     8
#define OCPG    8
#define REPD    32
#define H       256
#define Wd      256
#define PLANE   (H * Wd)             // 65536
#define PLANE4  (PLANE / 4)          // 16384
#define NWTS    (OCPG * 9)           // 72

// Tile: full image width x 32 rows; 256 threads, 4 blocks/SM (single wave)
#define TY      32
#define NTHR    256
#define SROWS   (TY + 2)             // 34
#define SSTR    260                  // floats per smem row (16B aligned)
#define SSTR4   (SSTR / 4)

// ---------------------------------------------------------------------------
// Fused kernel: weight-gen + channel-sum (reflect pad) + 3x3 dynamic conv.
// grid: (H/TY, B*G) = (8, 64) = 512 blocks (one full wave at 4/SM).
// Phase 2: thread = (x-quad q, oc-pair {p, p+4}), 32 rows sliding window.
// Edge taps from conflict-free side arrays Sx/Sw. Streaming stores.
// ---------------------------------------------------------------------------
__global__ __launch_bounds__(NTHR, 4)
void dyn_conv(const float* __restrict__ x,
              const float* __restrict__ rep,
              const float* __restrict__ Wm,
              float* __restrict__ out) {
    const int bg = blockIdx.y;
    const int b  = bg >> 3;
    const int g  = bg & 7;
    const int y0 = blockIdx.x * TY;
    const int t  = threadIdx.x;

    __shared__ __align__(16) float S[SROWS * SSTR];
    __shared__ float Sx[SROWS * 64];   // quad.x per (row, quad)
    __shared__ float Sw[SROWS * 64];   // quad.w per (row, quad)
    __shared__ float wsh[NWTS];
    __shared__ float rsh[REPD];

    // ---- weight generation (tiny; W is L2-resident) ----
    if (t < REPD) rsh[t] = rep[b * REPD + t];
    __syncthreads();
    if (t < NWTS) {
        const float* wrow = Wm + (size_t)(g * NWTS + t) * REPD;
        float acc = 0.f;
#pragma unroll
        for (int j = 0; j < REPD; ++j) acc = fmaf(rsh[j], wrow[j], acc);
        wsh[t] = acc > 0.f ? acc : 0.1f * acc;
    }

    // ---- Phase 1: channel-sum 34 full-width rows into smem (all float4) ----
    const float4* xb = (const float4*)x + ((size_t)(b * C + g * FPG)) * PLANE4;
    for (int idx = t; idx < SROWS * 64; idx += NTHR) {   // 2176 float4s
        const int r  = idx >> 6;
        const int q4 = idx & 63;
        int yy = y0 - 1 + r;
        yy = (yy < 0) ? -yy : yy;
        yy = (yy >= H) ? (2 * H - 2 - yy) : yy;
        const float4* p = xb + (size_t)yy * 64 + q4;
        float4 s = p[0];
#pragma unroll
        for (int ch = 1; ch < FPG; ++ch) {
            const float4 v = p[(size_t)ch * PLANE4];
            s.x += v.x; s.y += v.y; s.z += v.z; s.w += v.w;
        }
        ((float4*)S)[r * SSTR4 + q4] = s;
        Sx[r * 64 + q4] = s.x;
        Sw[r * 64 + q4] = s.w;
    }
    __syncthreads();

    // ---- Phase 2: 3x3 conv, 2 output channels (p, p+4), 32 rows ----
    const int q  = t & 63;            // x-quad: output cols 4q..4q+3
    const int p  = t >> 6;            // 0..3 -> channels p and p+4

    float w0[9], w1[9];
#pragma unroll
    for (int k = 0; k < 9; ++k) {
        w0[k] = wsh[p * 9 + k];
        w1[k] = wsh[(p + 4) * 9 + k];
    }

    // conflict-free side-array indices (clamped; edge lanes use own v.y/v.z)
    const int qm = (q == 0)  ? 0  : q - 1;
    const int qp = (q == 63) ? 63 : q + 1;

    float* o0s = out + ((size_t)(b * C + g * OCPG + p)) * PLANE
                     + (size_t)y0 * Wd + 4 * q;
    float* o1s = o0s + 4 * PLANE;     // channel p+4

    // sliding 6-wide window rows: a = top, m = mid
    float a0,a1,a2,a3,a4,a5, m0,m1,m2,m3,m4,m5;
    {
        const float4 v = *(const float4*)&S[0 * SSTR + 4 * q];
        const float l = Sw[0 * 64 + qm], rr = Sx[0 * 64 + qp];
        a1 = v.x; a2 = v.y; a3 = v.z; a4 = v.w;
        a0 = (q == 0)  ? v.y : l;
        a5 = (q == 63) ? v.z : rr;
    }
    {
        const float4 v = *(const float4*)&S[1 * SSTR + 4 * q];
        const float l = Sw[1 * 64 + qm], rr = Sx[1 * 64 + qp];
        m1 = v.x; m2 = v.y; m3 = v.z; m4 = v.w;
        m0 = (q == 0)  ? v.y : l;
        m5 = (q == 63) ? v.z : rr;
    }

#pragma unroll 8
    for (int r = 0; r < TY; ++r) {
        const float4 v = *(const float4*)&S[(r + 2) * SSTR + 4 * q];
        const float l = Sw[(r + 2) * 64 + qm], rr = Sx[(r + 2) * 64 + qp];
        const float c1 = v.x, c2 = v.y, c3 = v.z, c4 = v.w;
        const float c0 = (q == 0)  ? v.y : l;
        const float c5 = (q == 63) ? v.z : rr;

        float4 u, s;
        u.x =      w0[0]*a0;          s.x =      w1[0]*a0;
        u.x = fmaf(w0[1],a1,u.x);     s.x = fmaf(w1[1],a1,s.x);
        u.x = fmaf(w0[2],a2,u.x);     s.x = fmaf(w1[2],a2,s.x);
        u.x = fmaf(w0[3],m0,u.x);     s.x = fmaf(w1[3],m0,s.x);
        u.x = fmaf(w0[4],m1,u.x);     s.x = fmaf(w1[4],m1,s.x);
        u.x = fmaf(w0[5],m2,u.x);     s.x = fmaf(w1[5],m2,s.x);
        u.x = fmaf(w0[6],c0,u.x);     s.x = fmaf(w1[6],c0,s.x);
        u.x = fmaf(w0[7],c1,u.x);     s.x = fmaf(w1[7],c1,s.x);
        u.x = fmaf(w0[8],c2,u.x);     s.x = fmaf(w1[8],c2,s.x);

        u.y =      w0[0]*a1;          s.y =      w1[0]*a1;
        u.y = fmaf(w0[1],a2,u.y);     s.y = fmaf(w1[1],a2,s.y);
        u.y = fmaf(w0[2],a3,u.y);     s.y = fmaf(w1[2],a3,s.y);
        u.y = fmaf(w0[3],m1,u.y);     s.y = fmaf(w1[3],m1,s.y);
        u.y = fmaf(w0[4],m2,u.y);     s.y = fmaf(w1[4],m2,s.y);
        u.y = fmaf(w0[5],m3,u.y);     s.y = fmaf(w1[5],m3,s.y);
        u.y = fmaf(w0[6],c1,u.y);     s.y = fmaf(w1[6],c1,s.y);
        u.y = fmaf(w0[7],c2,u.y);     s.y = fmaf(w1[7],c2,s.y);
        u.y = fmaf(w0[8],c3,u.y);     s.y = fmaf(w1[8],c3,s.y);

        u.z =      w0[0]*a2;          s.z =      w1[0]*a2;
        u.z = fmaf(w0[1],a3,u.z);     s.z = fmaf(w1[1],a3,s.z);
        u.z = fmaf(w0[2],a4,u.z);     s.z = fmaf(w1[2],a4,s.z);
        u.z = fmaf(w0[3],m2,u.z);     s.z = fmaf(w1[3],m2,s.z);
        u.z = fmaf(w0[4],m3,u.z);     s.z = fmaf(w1[4],m3,s.z);
        u.z = fmaf(w0[5],m4,u.z);     s.z = fmaf(w1[5],m4,s.z);
        u.z = fmaf(w0[6],c2,u.z);     s.z = fmaf(w1[6],c2,s.z);
        u.z = fmaf(w0[7],c3,u.z);     s.z = fmaf(w1[7],c3,s.z);
        u.z = fmaf(w0[8],c4,u.z);     s.z = fmaf(w1[8],c4,s.z);

        u.w =      w0[0]*a3;          s.w =      w1[0]*a3;
        u.w = fmaf(w0[1],a4,u.w);     s.w = fmaf(w1[1],a4,s.w);
        u.w = fmaf(w0[2],a5,u.w);     s.w = fmaf(w1[2],a5,s.w);
        u.w = fmaf(w0[3],m3,u.w);     s.w = fmaf(w1[3],m3,s.w);
        u.w = fmaf(w0[4],m4,u.w);     s.w = fmaf(w1[4],m4,s.w);
        u.w = fmaf(w0[5],m5,u.w);     s.w = fmaf(w1[5],m5,s.w);
        u.w = fmaf(w0[6],c3,u.w);     s.w = fmaf(w1[6],c3,s.w);
        u.w = fmaf(w0[7],c4,u.w);     s.w = fmaf(w1[7],c4,s.w);
        u.w = fmaf(w0[8],c5,u.w);     s.w = fmaf(w1[8],c5,s.w);

        __stcs((float4*)(o0s + (size_t)r * Wd), u);   // streaming store
        __stcs((float4*)(o1s + (size_t)r * Wd), s);

        a0=m0; a1=m1; a2=m2; a3=m3; a4=m4; a5=m5;
        m0=c0; m1=c1; m2=c2; m3=c3; m4=c4; m5=c5;
    }
}

// ---------------------------------------------------------------------------
extern "C" void kernel_launch(void* const* d_in, const int* in_sizes, int n_in,
                              void* d_out, int out_size) {
    const float* x   = (const float*)d_in[0];
    const float* rep = (const float*)d_in[1];
    const float* Wm  = (const float*)d_in[2];
    float* out = (float*)d_out;

    dim3 grid(H / TY, B * G);
    dyn_conv<<<grid, NTHR>>>(x, rep, Wm, out);
}

// round 14
// speedup vs baseline: 1.0930x; 1.0930x over previous
#include <cuda_runtime.h>

// Problem constants
#define B       8
#define C       64
#define G       8
#define FPG     8
#define OCPG    8
#define REPD    32
#define H       256
#define Wd      256
#define PLANE   (H * Wd)             // 65536
#define PLANE4  (PLANE / 4)          // 16384
#define NWTS    (OCPG * 9)           // 72

// Tile: full image width x 16 rows
#define TY      16
#define NTHR    256
#define SROWS   (TY + 2)             // 18
#define SSTR    260                  // floats per smem row (16B aligned)
#define SSTR4   (SSTR / 4)

// ---------------------------------------------------------------------------
// Fused kernel: weight-gen + channel-sum (reflect pad) + 3x3 dynamic conv.
// grid: (H/TY, B*G), block 256.  Target 5 blocks/SM (51-reg cap, 32-bit
// output addressing).  Phase 2: thread = (x-quad q, oc-pair {p, p+4}).
// Edge taps from conflict-free side arrays Sx/Sw. Streaming stores.
// ---------------------------------------------------------------------------
__global__ __launch_bounds__(NTHR, 5)
void dyn_conv(const float* __restrict__ x,
              const float* __restrict__ rep,
              const float* __restrict__ Wm,
              float* __restrict__ out) {
    const int bg = blockIdx.y;
    const int b  = bg >> 3;
    const int g  = bg & 7;
    const int y0 = blockIdx.x * TY;
    const int t  = threadIdx.x;

    __shared__ __align__(16) float S[SROWS * SSTR];
    __shared__ float Sx[SROWS * 64];   // quad.x per (row, quad)
    __shared__ float Sw[SROWS * 64];   // quad.w per (row, quad)
    __shared__ float wsh[NWTS];
    __shared__ float rsh[REPD];

    // ---- weight generation (tiny; W is L2-resident) ----
    if (t < REPD) rsh[t] = rep[b * REPD + t];
    __syncthreads();
    if (t < NWTS) {
        const float* wrow = Wm + (unsigned)(g * NWTS + t) * REPD;
        float acc = 0.f;
#pragma unroll
        for (int j = 0; j < REPD; ++j) acc = fmaf(rsh[j], wrow[j], acc);
        wsh[t] = acc > 0.f ? acc : 0.1f * acc;
    }

    // ---- Phase 1: channel-sum 18 full-width rows into smem (all float4) ----
    const float4* xb = (const float4*)x + (unsigned)(b * C + g * FPG) * PLANE4;
    const bool interior = (blockIdx.x != 0) & (blockIdx.x != gridDim.x - 1);
#pragma unroll
    for (int idx = t; idx < SROWS * 64; idx += NTHR) {   // 1152 float4s
        const int r  = idx >> 6;
        const int q4 = idx & 63;
        int yy = y0 - 1 + r;
        if (!interior) {                       // reflect only at image edges
            yy = (yy < 0) ? -yy : yy;
            yy = (yy >= H) ? (2 * H - 2 - yy) : yy;
        }
        const float4* p = xb + (unsigned)yy * 64 + q4;
        float4 s = p[0];
#pragma unroll
        for (int ch = 1; ch < FPG; ++ch) {
            const float4 v = p[(unsigned)ch * PLANE4];
            s.x += v.x; s.y += v.y; s.z += v.z; s.w += v.w;
        }
        ((float4*)S)[r * SSTR4 + q4] = s;
        Sx[r * 64 + q4] = s.x;
        Sw[r * 64 + q4] = s.w;
    }
    __syncthreads();

    // ---- Phase 2: 3x3 conv, 2 output channels (p, p+4), 16 rows ----
    const int q  = t & 63;            // x-quad: output cols 4q..4q+3
    const int p  = t >> 6;            // 0..3 -> channels p and p+4

    float w0[9], w1[9];
#pragma unroll
    for (int k = 0; k < 9; ++k) {
        w0[k] = wsh[p * 9 + k];
        w1[k] = wsh[(p + 4) * 9 + k];
    }

    // conflict-free side-array indices (clamped; edge lanes use own v.y/v.z)
    const int qm = (q == 0)  ? 0  : q - 1;
    const int qp = (q == 63) ? 63 : q + 1;

    // 32-bit element offsets (max < 2^24 elements * ... < 2^31)
    const unsigned obase0 = (unsigned)(b * C + g * OCPG + p) * PLANE
                          + (unsigned)y0 * Wd + 4u * q;
    const unsigned obase1 = obase0 + 4u * PLANE;

    // sliding 6-wide window rows: a = top, m = mid
    float a0,a1,a2,a3,a4,a5, m0,m1,m2,m3,m4,m5;
    {
        const float4 v = *(const float4*)&S[0 * SSTR + 4 * q];
        const float l = Sw[0 * 64 + qm], rr = Sx[0 * 64 + qp];
        a1 = v.x; a2 = v.y; a3 = v.z; a4 = v.w;
        a0 = (q == 0)  ? v.y : l;
        a5 = (q == 63) ? v.z : rr;
    }
    {
        const float4 v = *(const float4*)&S[1 * SSTR + 4 * q];
        const float l = Sw[1 * 64 + qm], rr = Sx[1 * 64 + qp];
        m1 = v.x; m2 = v.y; m3 = v.z; m4 = v.w;
        m0 = (q == 0)  ? v.y : l;
        m5 = (q == 63) ? v.z : rr;
    }

#pragma unroll
    for (int r = 0; r < TY; ++r) {
        const float4 v = *(const float4*)&S[(r + 2) * SSTR + 4 * q];
        const float l = Sw[(r + 2) * 64 + qm], rr = Sx[(r + 2) * 64 + qp];
        const float c1 = v.x, c2 = v.y, c3 = v.z, c4 = v.w;
        const float c0 = (q == 0)  ? v.y : l;
        const float c5 = (q == 63) ? v.z : rr;

        float4 u, s;
        u.x =      w0[0]*a0;          s.x =      w1[0]*a0;
        u.x = fmaf(w0[1],a1,u.x);     s.x = fmaf(w1[1],a1,s.x);
        u.x = fmaf(w0[2],a2,u.x);     s.x = fmaf(w1[2],a2,s.x);
        u.x = fmaf(w0[3],m0,u.x);     s.x = fmaf(w1[3],m0,s.x);
        u.x = fmaf(w0[4],m1,u.x);     s.x = fmaf(w1[4],m1,s.x);
        u.x = fmaf(w0[5],m2,u.x);     s.x = fmaf(w1[5],m2,s.x);
        u.x = fmaf(w0[6],c0,u.x);     s.x = fmaf(w1[6],c0,s.x);
        u.x = fmaf(w0[7],c1,u.x);     s.x = fmaf(w1[7],c1,s.x);
        u.x = fmaf(w0[8],c2,u.x);     s.x = fmaf(w1[8],c2,s.x);

        u.y =      w0[0]*a1;          s.y =      w1[0]*a1;
        u.y = fmaf(w0[1],a2,u.y);     s.y = fmaf(w1[1],a2,s.y);
        u.y = fmaf(w0[2],a3,u.y);     s.y = fmaf(w1[2],a3,s.y);
        u.y = fmaf(w0[3],m1,u.y);     s.y = fmaf(w1[3],m1,s.y);
        u.y = fmaf(w0[4],m2,u.y);     s.y = fmaf(w1[4],m2,s.y);
        u.y = fmaf(w0[5],m3,u.y);     s.y = fmaf(w1[5],m3,s.y);
        u.y = fmaf(w0[6],c1,u.y);     s.y = fmaf(w1[6],c1,s.y);
        u.y = fmaf(w0[7],c2,u.y);     s.y = fmaf(w1[7],c2,s.y);
        u.y = fmaf(w0[8],c3,u.y);     s.y = fmaf(w1[8],c3,s.y);

        u.z =      w0[0]*a2;          s.z =      w1[0]*a2;
        u.z = fmaf(w0[1],a3,u.z);     s.z = fmaf(w1[1],a3,s.z);
        u.z = fmaf(w0[2],a4,u.z);     s.z = fmaf(w1[2],a4,s.z);
        u.z = fmaf(w0[3],m2,u.z);     s.z = fmaf(w1[3],m2,s.z);
        u.z = fmaf(w0[4],m3,u.z);     s.z = fmaf(w1[4],m3,s.z);
        u.z = fmaf(w0[5],m4,u.z);     s.z = fmaf(w1[5],m4,s.z);
        u.z = fmaf(w0[6],c2,u.z);     s.z = fmaf(w1[6],c2,s.z);
        u.z = fmaf(w0[7],c3,u.z);     s.z = fmaf(w1[7],c3,s.z);
        u.z = fmaf(w0[8],c4,u.z);     s.z = fmaf(w1[8],c4,s.z);

        u.w =      w0[0]*a3;          s.w =      w1[0]*a3;
        u.w = fmaf(w0[1],a4,u.w);     s.w = fmaf(w1[1],a4,s.w);
        u.w = fmaf(w0[2],a5,u.w);     s.w = fmaf(w1[2],a5,s.w);
        u.w = fmaf(w0[3],m3,u.w);     s.w = fmaf(w1[3],m3,s.w);
        u.w = fmaf(w0[4],m4,u.w);     s.w = fmaf(w1[4],m4,s.w);
        u.w = fmaf(w0[5],m5,u.w);     s.w = fmaf(w1[5],m5,s.w);
        u.w = fmaf(w0[6],c3,u.w);     s.w = fmaf(w1[6],c3,s.w);
        u.w = fmaf(w0[7],c4,u.w);     s.w = fmaf(w1[7],c4,s.w);
        u.w = fmaf(w0[8],c5,u.w);     s.w = fmaf(w1[8],c5,s.w);

        __stcs((float4*)(out + obase0 + (unsigned)r * Wd), u);
        __stcs((float4*)(out + obase1 + (unsigned)r * Wd), s);

        a0=m0; a1=m1; a2=m2; a3=m3; a4=m4; a5=m5;
        m0=c0; m1=c1; m2=c2; m3=c3; m4=c4; m5=c5;
    }
}

// ---------------------------------------------------------------------------
extern "C" void kernel_launch(void* const* d_in, const int* in_sizes, int n_in,
                              void* d_out, int out_size) {
    const float* x   = (const float*)d_in[0];
    const float* rep = (const float*)d_in[1];
    const float* Wm  = (const float*)d_in[2];
    float* out = (float*)d_out;

    dim3 grid(H / TY, B * G);
    dyn_conv<<<grid, NTHR>>>(x, rep, Wm, out);
}

// round 15
// speedup vs baseline: 1.2745x; 1.1661x over previous
#include <cuda_runtime.h>

// Problem constants
#define B       8
#define C       64
#define G       8
#define FPG     8
#define OCPG    8
#define REPD    32
#define H       256
#define Wd      256
#define PLANE   (H * Wd)             // 65536
#define PLANE4  (PLANE / 4)          // 16384
#define NWTS    (OCPG * 9)           // 72

// Tile: full image width x 16 rows
#define TY      16
#define NTHR    256
#define SROWS   (TY + 2)             // 18
#define SSTR    260                  // floats per smem row (16B aligned)
#define SSTR4   (SSTR / 4)

// ---------------------------------------------------------------------------
// Fused kernel: weight-gen + channel-sum (reflect pad) + 3x3 dynamic conv.
// grid: (H/TY, B*G), block 256, 4 blocks/SM.
// Phase 2: thread = (x-quad q, oc-pair {p, p+4}), 16 rows sliding window.
// Edge taps served by conflict-free side arrays Sx (quad.x) / Sw (quad.w).
// Output via streaming stores (write-once data, evict-first).
// ---------------------------------------------------------------------------
__global__ __launch_bounds__(NTHR, 4)
void dyn_conv(const float* __restrict__ x,
              const float* __restrict__ rep,
              const float* __restrict__ Wm,
              float* __restrict__ out) {
    const int bg = blockIdx.y;
    const int b  = bg >> 3;
    const int g  = bg & 7;
    const int y0 = blockIdx.x * TY;
    const int t  = threadIdx.x;

    __shared__ __align__(16) float S[SROWS * SSTR];
    __shared__ float Sx[SROWS * 64];   // quad.x per (row, quad)
    __shared__ float Sw[SROWS * 64];   // quad.w per (row, quad)
    __shared__ float wsh[NWTS];
    __shared__ float rsh[REPD];

    // ---- weight generation (tiny; W is L2-resident) ----
    if (t < REPD) rsh[t] = rep[b * REPD + t];
    __syncthreads();
    if (t < NWTS) {
        const float* wrow = Wm + (size_t)(g * NWTS + t) * REPD;
        float acc = 0.f;
#pragma unroll
        for (int j = 0; j < REPD; ++j) acc = fmaf(rsh[j], wrow[j], acc);
        wsh[t] = acc > 0.f ? acc : 0.1f * acc;
    }

    // ---- Phase 1: channel-sum 18 full-width rows into smem (all float4) ----
    const float4* xb = (const float4*)x + ((size_t)(b * C + g * FPG)) * PLANE4;
#pragma unroll
    for (int idx = t; idx < SROWS * 64; idx += NTHR) {   // 1152 float4s
        const int r  = idx >> 6;
        const int q4 = idx & 63;
        int yy = y0 - 1 + r;
        yy = (yy < 0) ? -yy : yy;
        yy = (yy >= H) ? (2 * H - 2 - yy) : yy;
        const float4* p = xb + (size_t)yy * 64 + q4;
        float4 s = p[0];
#pragma unroll
        for (int ch = 1; ch < FPG; ++ch) {
            const float4 v = p[(size_t)ch * PLANE4];
            s.x += v.x; s.y += v.y; s.z += v.z; s.w += v.w;
        }
        ((float4*)S)[r * SSTR4 + q4] = s;
        Sx[r * 64 + q4] = s.x;
        Sw[r * 64 + q4] = s.w;
    }
    __syncthreads();

    // ---- Phase 2: 3x3 conv, 2 output channels (p, p+4), 16 rows ----
    const int q  = t & 63;            // x-quad: output cols 4q..4q+3
    const int p  = t >> 6;            // 0..3 -> channels p and p+4

    float w0[9], w1[9];
#pragma unroll
    for (int k = 0; k < 9; ++k) {
        w0[k] = wsh[p * 9 + k];
        w1[k] = wsh[(p + 4) * 9 + k];
    }

    // conflict-free side-array indices (clamped; edge lanes use own v.y/v.z)
    const int qm = (q == 0)  ? 0  : q - 1;
    const int qp = (q == 63) ? 63 : q + 1;

    float* o0s = out + ((size_t)(b * C + g * OCPG + p)) * PLANE
                     + (size_t)y0 * Wd + 4 * q;
    float* o1s = o0s + 4 * PLANE;     // channel p+4

    // sliding 6-wide window rows: a = top, m = mid
    float a0,a1,a2,a3,a4,a5, m0,m1,m2,m3,m4,m5;
    {
        const float4 v = *(const float4*)&S[0 * SSTR + 4 * q];
        const float l = Sw[0 * 64 + qm], rr = Sx[0 * 64 + qp];
        a1 = v.x; a2 = v.y; a3 = v.z; a4 = v.w;
        a0 = (q == 0)  ? v.y : l;
        a5 = (q == 63) ? v.z : rr;
    }
    {
        const float4 v = *(const float4*)&S[1 * SSTR + 4 * q];
        const float l = Sw[1 * 64 + qm], rr = Sx[1 * 64 + qp];
        m1 = v.x; m2 = v.y; m3 = v.z; m4 = v.w;
        m0 = (q == 0)  ? v.y : l;
        m5 = (q == 63) ? v.z : rr;
    }

#pragma unroll
    for (int r = 0; r < TY; ++r) {
        const float4 v = *(const float4*)&S[(r + 2) * SSTR + 4 * q];
        const float l = Sw[(r + 2) * 64 + qm], rr = Sx[(r + 2) * 64 + qp];
        const float c1 = v.x, c2 = v.y, c3 = v.z, c4 = v.w;
        const float c0 = (q == 0)  ? v.y : l;
        const float c5 = (q == 63) ? v.z : rr;

        float4 u, s;
        u.x =      w0[0]*a0;          s.x =      w1[0]*a0;
        u.x = fmaf(w0[1],a1,u.x);     s.x = fmaf(w1[1],a1,s.x);
        u.x = fmaf(w0[2],a2,u.x);     s.x = fmaf(w1[2],a2,s.x);
        u.x = fmaf(w0[3],m0,u.x);     s.x = fmaf(w1[3],m0,s.x);
        u.x = fmaf(w0[4],m1,u.x);     s.x = fmaf(w1[4],m1,s.x);
        u.x = fmaf(w0[5],m2,u.x);     s.x = fmaf(w1[5],m2,s.x);
        u.x = fmaf(w0[6],c0,u.x);     s.x = fmaf(w1[6],c0,s.x);
        u.x = fmaf(w0[7],c1,u.x);     s.x = fmaf(w1[7],c1,s.x);
        u.x = fmaf(w0[8],c2,u.x);     s.x = fmaf(w1[8],c2,s.x);

        u.y =      w0[0]*a1;          s.y =      w1[0]*a1;
        u.y = fmaf(w0[1],a2,u.y);     s.y = fmaf(w1[1],a2,s.y);
        u.y = fmaf(w0[2],a3,u.y);     s.y = fmaf(w1[2],a3,s.y);
        u.y = fmaf(w0[3],m1,u.y);     s.y = fmaf(w1[3],m1,s.y);
        u.y = fmaf(w0[4],m2,u.y);     s.y = fmaf(w1[4],m2,s.y);
        u.y = fmaf(w0[5],m3,u.y);     s.y = fmaf(w1[5],m3,s.y);
        u.y = fmaf(w0[6],c1,u.y);     s.y = fmaf(w1[6],c1,s.y);
        u.y = fmaf(w0[7],c2,u.y);     s.y = fmaf(w1[7],c2,s.y);
        u.y = fmaf(w0[8],c3,u.y);     s.y = fmaf(w1[8],c3,s.y);

        u.z =      w0[0]*a2;          s.z =      w1[0]*a2;
        u.z = fmaf(w0[1],a3,u.z);     s.z = fmaf(w1[1],a3,s.z);
        u.z = fmaf(w0[2],a4,u.z);     s.z = fmaf(w1[2],a4,s.z);
        u.z = fmaf(w0[3],m2,u.z);     s.z = fmaf(w1[3],m2,s.z);
        u.z = fmaf(w0[4],m3,u.z);     s.z = fmaf(w1[4],m3,s.z);
        u.z = fmaf(w0[5],m4,u.z);     s.z = fmaf(w1[5],m4,s.z);
        u.z = fmaf(w0[6],c2,u.z);     s.z = fmaf(w1[6],c2,s.z);
        u.z = fmaf(w0[7],c3,u.z);     s.z = fmaf(w1[7],c3,s.z);
        u.z = fmaf(w0[8],c4,u.z);     s.z = fmaf(w1[8],c4,s.z);

        u.w =      w0[0]*a3;          s.w =      w1[0]*a3;
        u.w = fmaf(w0[1],a4,u.w);     s.w = fmaf(w1[1],a4,s.w);
        u.w = fmaf(w0[2],a5,u.w);     s.w = fmaf(w1[2],a5,s.w);
        u.w = fmaf(w0[3],m3,u.w);     s.w = fmaf(w1[3],m3,s.w);
        u.w = fmaf(w0[4],m4,u.w);     s.w = fmaf(w1[4],m4,s.w);
        u.w = fmaf(w0[5],m5,u.w);     s.w = fmaf(w1[5],m5,s.w);
        u.w = fmaf(w0[6],c3,u.w);     s.w = fmaf(w1[6],c3,s.w);
        u.w = fmaf(w0[7],c4,u.w);     s.w = fmaf(w1[7],c4,s.w);
        u.w = fmaf(w0[8],c5,u.w);     s.w = fmaf(w1[8],c5,s.w);

        __stcs((float4*)(o0s + (size_t)r * Wd), u);   // streaming store
        __stcs((float4*)(o1s + (size_t)r * Wd), s);

        a0=m0; a1=m1; a2=m2; a3=m3; a4=m4; a5=m5;
        m0=c0; m1=c1; m2=c2; m3=c3; m4=c4; m5=c5;
    }
}

// ---------------------------------------------------------------------------
extern "C" void kernel_launch(void* const* d_in, const int* in_sizes, int n_in,
                              void* d_out, int out_size) {
    const float* x   = (const float*)d_in[0];
    const float* rep = (const float*)d_in[1];
    const float* Wm  = (const float*)d_in[2];
    float* out = (float*)d_out;

    dim3 grid(H / TY, B * G);
    dyn_conv<<<grid, NTHR>>>(x, rep, Wm, out);
}

// round 16
// speedup vs baseline: 1.2803x; 1.0045x over previous
#include <cuda_runtime.h>

// Problem constants
#define B       8
#define C       64
#define G       8
#define FPG     8
#define OCPG    8
#define REPD    32
#define H       256
#define Wd      256
#define PLANE   (H * Wd)             // 65536
#define PLANE4  (PLANE / 4)          // 16384
#define NWTS    (OCPG * 9)           // 72

// Tile: full image width x 16 rows
#define TY      16
#define NTHR    256
#define SROWS   (TY + 2)             // 18
#define SSTR    260                  // floats per smem row (16B aligned)
#define SSTR4   (SSTR / 4)

// ---------------------------------------------------------------------------
// Fused kernel: weight-gen + channel-sum (reflect pad) + 3x3 dynamic conv.
// grid: (H/TY, B*G), block 256, 4 blocks/SM.
// Phase 2: thread = (x-quad q, oc-pair {p, p+4}), 16 rows sliding window.
// Edge taps served by conflict-free side arrays Sx (quad.x) / Sw (quad.w).
// Interior y-tiles use a clamp-free load path; streaming stores on output.
// ---------------------------------------------------------------------------
__global__ __launch_bounds__(NTHR, 4)
void dyn_conv(const float* __restrict__ x,
              const float* __restrict__ rep,
              const float* __restrict__ Wm,
              float* __restrict__ out) {
    const int bg = blockIdx.y;
    const int b  = bg >> 3;
    const int g  = bg & 7;
    const int y0 = blockIdx.x * TY;
    const int t  = threadIdx.x;

    __shared__ __align__(16) float S[SROWS * SSTR];
    __shared__ float Sx[SROWS * 64];   // quad.x per (row, quad)
    __shared__ float Sw[SROWS * 64];   // quad.w per (row, quad)
    __shared__ float wsh[NWTS];
    __shared__ float rsh[REPD];

    // ---- weight generation (tiny; W is L2-resident) ----
    if (t < REPD) rsh[t] = rep[b * REPD + t];
    __syncthreads();
    if (t < NWTS) {
        const float* wrow = Wm + (size_t)(g * NWTS + t) * REPD;
        float acc = 0.f;
#pragma unroll
        for (int j = 0; j < REPD; ++j) acc = fmaf(rsh[j], wrow[j], acc);
        wsh[t] = acc > 0.f ? acc : 0.1f * acc;
    }

    // ---- Phase 1: channel-sum 18 full-width rows into smem ----
    // 1152 float4s / 256 threads = 4 full iterations + half iteration (t<128).
    const float4* xb = (const float4*)x + ((size_t)(b * C + g * FPG)) * PLANE4;

    if (blockIdx.x != 0 && blockIdx.x != gridDim.x - 1) {
        // interior: no reflect clamps needed
#pragma unroll
        for (int it = 0; it < 5; ++it) {
            const int idx = t + it * NTHR;
            if (it == 4 && t >= 128) break;
            const int r  = idx >> 6;
            const int q4 = idx & 63;
            const float4* p = xb + (size_t)(y0 - 1 + r) * 64 + q4;
            float4 s = p[0];
#pragma unroll
            for (int ch = 1; ch < FPG; ++ch) {
                const float4 v = p[(size_t)ch * PLANE4];
                s.x += v.x; s.y += v.y; s.z += v.z; s.w += v.w;
            }
            ((float4*)S)[r * SSTR4 + q4] = s;
            Sx[r * 64 + q4] = s.x;
            Sw[r * 64 + q4] = s.w;
        }
    } else {
        // boundary tiles: reflect-pad in y
#pragma unroll
        for (int it = 0; it < 5; ++it) {
            const int idx = t + it * NTHR;
            if (it == 4 && t >= 128) break;
            const int r  = idx >> 6;
            const int q4 = idx & 63;
            int yy = y0 - 1 + r;
            yy = (yy < 0) ? -yy : yy;
            yy = (yy >= H) ? (2 * H - 2 - yy) : yy;
            const float4* p = xb + (size_t)yy * 64 + q4;
            float4 s = p[0];
#pragma unroll
            for (int ch = 1; ch < FPG; ++ch) {
                const float4 v = p[(size_t)ch * PLANE4];
                s.x += v.x; s.y += v.y; s.z += v.z; s.w += v.w;
            }
            ((float4*)S)[r * SSTR4 + q4] = s;
            Sx[r * 64 + q4] = s.x;
            Sw[r * 64 + q4] = s.w;
        }
    }
    __syncthreads();

    // ---- Phase 2: 3x3 conv, 2 output channels (p, p+4), 16 rows ----
    const int q  = t & 63;            // x-quad: output cols 4q..4q+3
    const int p  = t >> 6;            // 0..3 -> channels p and p+4

    float w0[9], w1[9];
#pragma unroll
    for (int k = 0; k < 9; ++k) {
        w0[k] = wsh[p * 9 + k];
        w1[k] = wsh[(p + 4) * 9 + k];
    }

    // conflict-free side-array indices (clamped; edge lanes use own v.y/v.z)
    const int qm = (q == 0)  ? 0  : q - 1;
    const int qp = (q == 63) ? 63 : q + 1;

    float* o0s = out + ((size_t)(b * C + g * OCPG + p)) * PLANE
                     + (size_t)y0 * Wd + 4 * q;
    float* o1s = o0s + 4 * PLANE;     // channel p+4

    // sliding 6-wide window rows: a = top, m = mid
    float a0,a1,a2,a3,a4,a5, m0,m1,m2,m3,m4,m5;
    {
        const float4 v = *(const float4*)&S[0 * SSTR + 4 * q];
        const float l = Sw[0 * 64 + qm], rr = Sx[0 * 64 + qp];
        a1 = v.x; a2 = v.y; a3 = v.z; a4 = v.w;
        a0 = (q == 0)  ? v.y : l;
        a5 = (q == 63) ? v.z : rr;
    }
    {
        const float4 v = *(const float4*)&S[1 * SSTR + 4 * q];
        const float l = Sw[1 * 64 + qm], rr = Sx[1 * 64 + qp];
        m1 = v.x; m2 = v.y; m3 = v.z; m4 = v.w;
        m0 = (q == 0)  ? v.y : l;
        m5 = (q == 63) ? v.z : rr;
    }

#pragma unroll
    for (int r = 0; r < TY; ++r) {
        const float4 v = *(const float4*)&S[(r + 2) * SSTR + 4 * q];
        const float l = Sw[(r + 2) * 64 + qm], rr = Sx[(r + 2) * 64 + qp];
        const float c1 = v.x, c2 = v.y, c3 = v.z, c4 = v.w;
        const float c0 = (q == 0)  ? v.y : l;
        const float c5 = (q == 63) ? v.z : rr;

        float4 u, s;
        u.x =      w0[0]*a0;          s.x =      w1[0]*a0;
        u.x = fmaf(w0[1],a1,u.x);     s.x = fmaf(w1[1],a1,s.x);
        u.x = fmaf(w0[2],a2,u.x);     s.x = fmaf(w1[2],a2,s.x);
        u.x = fmaf(w0[3],m0,u.x);     s.x = fmaf(w1[3],m0,s.x);
        u.x = fmaf(w0[4],m1,u.x);     s.x = fmaf(w1[4],m1,s.x);
        u.x = fmaf(w0[5],m2,u.x);     s.x = fmaf(w1[5],m2,s.x);
        u.x = fmaf(w0[6],c0,u.x);     s.x = fmaf(w1[6],c0,s.x);
        u.x = fmaf(w0[7],c1,u.x);     s.x = fmaf(w1[7],c1,s.x);
        u.x = fmaf(w0[8],c2,u.x);     s.x = fmaf(w1[8],c2,s.x);

        u.y =      w0[0]*a1;          s.y =      w1[0]*a1;
        u.y = fmaf(w0[1],a2,u.y);     s.y = fmaf(w1[1],a2,s.y);
        u.y = fmaf(w0[2],a3,u.y);     s.y = fmaf(w1[2],a3,s.y);
        u.y = fmaf(w0[3],m1,u.y);     s.y = fmaf(w1[3],m1,s.y);
        u.y = fmaf(w0[4],m2,u.y);     s.y = fmaf(w1[4],m2,s.y);
        u.y = fmaf(w0[5],m3,u.y);     s.y = fmaf(w1[5],m3,s.y);
        u.y = fmaf(w0[6],c1,u.y);     s.y = fmaf(w1[6],c1,s.y);
        u.y = fmaf(w0[7],c2,u.y);     s.y = fmaf(w1[7],c2,s.y);
        u.y = fmaf(w0[8],c3,u.y);     s.y = fmaf(w1[8],c3,s.y);

        u.z =      w0[0]*a2;          s.z =      w1[0]*a2;
        u.z = fmaf(w0[1],a3,u.z);     s.z = fmaf(w1[1],a3,s.z);
        u.z = fmaf(w0[2],a4,u.z);     s.z = fmaf(w1[2],a4,s.z);
        u.z = fmaf(w0[3],m2,u.z);     s.z = fmaf(w1[3],m2,s.z);
        u.z = fmaf(w0[4],m3,u.z);     s.z = fmaf(w1[4],m3,s.z);
        u.z = fmaf(w0[5],m4,u.z);     s.z = fmaf(w1[5],m4,s.z);
        u.z = fmaf(w0[6],c2,u.z);     s.z = fmaf(w1[6],c2,s.z);
        u.z = fmaf(w0[7],c3,u.z);     s.z = fmaf(w1[7],c3,s.z);
        u.z = fmaf(w0[8],c4,u.z);     s.z = fmaf(w1[8],c4,s.z);

        u.w =      w0[0]*a3;          s.w =      w1[0]*a3;
        u.w = fmaf(w0[1],a4,u.w);     s.w = fmaf(w1[1],a4,s.w);
        u.w = fmaf(w0[2],a5,u.w);     s.w = fmaf(w1[2],a5,s.w);
        u.w = fmaf(w0[3],m3,u.w);     s.w = fmaf(w1[3],m3,s.w);
        u.w = fmaf(w0[4],m4,u.w);     s.w = fmaf(w1[4],m4,s.w);
        u.w = fmaf(w0[5],m5,u.w);     s.w = fmaf(w1[5],m5,s.w);
        u.w = fmaf(w0[6],c3,u.w);     s.w = fmaf(w1[6],c3,s.w);
        u.w = fmaf(w0[7],c4,u.w);     s.w = fmaf(w1[7],c4,s.w);
        u.w = fmaf(w0[8],c5,u.w);     s.w = fmaf(w1[8],c5,s.w);

        __stcs((float4*)(o0s + (size_t)r * Wd), u);   // streaming store
        __stcs((float4*)(o1s + (size_t)r * Wd), s);

        a0=m0; a1=m1; a2=m2; a3=m3; a4=m4; a5=m5;
        m0=c0; m1=c1; m2=c2; m3=c3; m4=c4; m5=c5;
    }
}

// ---------------------------------------------------------------------------
extern "C" void kernel_launch(void* const* d_in, const int* in_sizes, int n_in,
                              void* d_out, int out_size) {
    const float* x   = (const float*)d_in[0];
    const float* rep = (const float*)d_in[1];
    const float* Wm  = (const float*)d_in[2];
    float* out = (float*)d_out;

    dim3 grid(H / TY, B * G);
    dyn_conv<<<grid, NTHR>>>(x, rep, Wm, out);
}